// round 2
// baseline (speedup 1.0000x reference)
#include <cuda_runtime.h>
#include <cuda_bf16.h>
#include <math.h>

// ---------------------------------------------------------------------------
// Problem constants
// ---------------------------------------------------------------------------
#define BSZ   8192
#define DIN   4096
#define DMODEL 512
#define DFF   2048
#define NH    3
#define HD    256
#define OUTD  896

// ---------------------------------------------------------------------------
// Scratch (static device globals -- allowed; cudaMalloc is not)
// ---------------------------------------------------------------------------
__device__ float g_mem[(size_t)BSZ * DMODEL];   // h after input proj (== memory)
__device__ float g_h  [(size_t)BSZ * DMODEL];   // running residual stream
__device__ float g_t  [(size_t)BSZ * DMODEL];   // temp for attn V projections
__device__ float g_u  [(size_t)BSZ * DMODEL];   // layernorm outputs
__device__ float g_ff [(size_t)BSZ * DFF];      // FFN hidden
__device__ float g_z  [(size_t)BSZ * NH * HD];  // head hidden [B, NH, HD]

// ---------------------------------------------------------------------------
// GEMM: C[M,N] = A[M,K] @ B[K,N] + epilogue
// 128x128 block tile, BK=16, 256 threads, 8x8 per-thread microtile.
// All uses have M,N,K divisible by tile dims -> no bounds checks.
// gridDim.z batches independent GEMMs (heads); s* are per-z element strides.
// ---------------------------------------------------------------------------
#define BM 128
#define BN 128
#define BK 16
#define TM 8
#define TN 8

enum { EPI_BIAS = 0, EPI_BIAS_POS = 1, EPI_BIAS_ADD = 2, EPI_BIAS_GELU = 3 };

__device__ __forceinline__ float gelu_exact(float x) {
    return 0.5f * x * (1.0f + erff(x * 0.70710678118654752440f));
}

template <int EPI>
__global__ __launch_bounds__(256)
void sgemm_kernel(const float* __restrict__ A, int lda, size_t sA,
                  const float* __restrict__ B, int ldb, size_t sB,
                  const float* __restrict__ bias, size_t sBias,
                  const float* __restrict__ extra,  // pos vec (POS) or add matrix (ADD, ldc stride)
                  float* __restrict__ C, int ldc, size_t sC,
                  int K)
{
    __shared__ float As[BK][BM];
    __shared__ float Bs[BK][BN];

    const int tid = threadIdx.x;
    const int bx = blockIdx.x;   // N tile
    const int by = blockIdx.y;   // M tile
    const int bz = blockIdx.z;   // batched-head index
    const int tx = tid & 15;
    const int ty = tid >> 4;

    const float* Ab = A + (size_t)bz * sA + (size_t)by * BM * lda;
    const float* Bb = B + (size_t)bz * sB + (size_t)bx * BN;
    const float* biasb = bias + (size_t)bz * sBias;
    float* Cb = C + (size_t)bz * sC;

    // A loader mapping: 128 rows x 16 cols = 512 float4; 2 per thread
    const int arow = tid >> 2;          // 0..63
    const int acol = (tid & 3) * 4;     // 0,4,8,12
    // B loader mapping: 16 rows x 128 cols = 512 float4; 2 per thread
    const int brow = tid >> 5;          // 0..7
    const int bcol = (tid & 31) * 4;    // 0..124

    float acc[TM][TN];
#pragma unroll
    for (int i = 0; i < TM; i++)
#pragma unroll
        for (int j = 0; j < TN; j++) acc[i][j] = 0.0f;

    for (int k0 = 0; k0 < K; k0 += BK) {
        float4 a0 = *(const float4*)(Ab + (size_t)arow        * lda + k0 + acol);
        float4 a1 = *(const float4*)(Ab + (size_t)(arow + 64) * lda + k0 + acol);
        float4 b0 = *(const float4*)(Bb + (size_t)(k0 + brow)     * ldb + bcol);
        float4 b1 = *(const float4*)(Bb + (size_t)(k0 + brow + 8) * ldb + bcol);

        As[acol + 0][arow] = a0.x;  As[acol + 1][arow] = a0.y;
        As[acol + 2][arow] = a0.z;  As[acol + 3][arow] = a0.w;
        As[acol + 0][arow + 64] = a1.x;  As[acol + 1][arow + 64] = a1.y;
        As[acol + 2][arow + 64] = a1.z;  As[acol + 3][arow + 64] = a1.w;
        *(float4*)&Bs[brow][bcol]     = b0;
        *(float4*)&Bs[brow + 8][bcol] = b1;
        __syncthreads();

#pragma unroll
        for (int kk = 0; kk < BK; kk++) {
            float a[TM], b[TN];
#pragma unroll
            for (int i = 0; i < TM; i++) a[i] = As[kk][ty * TM + i];
#pragma unroll
            for (int j = 0; j < TN; j++) b[j] = Bs[kk][tx * TN + j];
#pragma unroll
            for (int i = 0; i < TM; i++)
#pragma unroll
                for (int j = 0; j < TN; j++) acc[i][j] = fmaf(a[i], b[j], acc[i][j]);
        }
        __syncthreads();
    }

    const int m0 = by * BM + ty * TM;
    const int n0 = bx * BN + tx * TN;
#pragma unroll
    for (int i = 0; i < TM; i++) {
        const int m = m0 + i;
#pragma unroll
        for (int j = 0; j < TN; j++) {
            const int n = n0 + j;
            float v = acc[i][j] + biasb[n];
            if (EPI == EPI_BIAS_POS)  v += extra[n];
            if (EPI == EPI_BIAS_ADD)  v += extra[(size_t)m * ldc + n];
            if (EPI == EPI_BIAS_GELU) v = gelu_exact(v);
            Cb[(size_t)m * ldc + n] = v;
        }
    }
}

// ---------------------------------------------------------------------------
// Block reduction (256 threads)
// ---------------------------------------------------------------------------
__device__ __forceinline__ float blockReduceSum256(float v) {
    __shared__ float sh[8];
    const int lane = threadIdx.x & 31;
    const int wid  = threadIdx.x >> 5;
#pragma unroll
    for (int o = 16; o > 0; o >>= 1) v += __shfl_xor_sync(0xffffffffu, v, o);
    if (lane == 0) sh[wid] = v;
    __syncthreads();
    float r;
    if (wid == 0) {
        r = sh[lane & 7];
#pragma unroll
        for (int o = 4; o > 0; o >>= 1) r += __shfl_xor_sync(0xffffffffu, r, o);
        if (lane == 0) sh[0] = r;
    }
    __syncthreads();
    r = sh[0];
    __syncthreads();   // protect sh for a subsequent call
    return r;
}

// LayerNorm over D=512, one block (256 threads) per row
__global__ __launch_bounds__(256)
void ln512_kernel(const float* __restrict__ in, const float* __restrict__ g,
                  const float* __restrict__ b, float* __restrict__ out)
{
    const int r = blockIdx.x;
    const int t = threadIdx.x;
    const float* xr = in + (size_t)r * DMODEL;
    float v0 = xr[t];
    float v1 = xr[t + 256];
    float mean = blockReduceSum256(v0 + v1) * (1.0f / 512.0f);
    float d0 = v0 - mean, d1 = v1 - mean;
    float var = blockReduceSum256(d0 * d0 + d1 * d1) * (1.0f / 512.0f);
    float rstd = rsqrtf(var + 1e-5f);
    float* orow = out + (size_t)r * DMODEL;
    orow[t]       = d0 * rstd * g[t]       + b[t];
    orow[t + 256] = d1 * rstd * g[t + 256] + b[t + 256];
}

// LayerNorm over HD=256 per (batch, head) row; gamma/beta per head
__global__ __launch_bounds__(256)
void ln_head_kernel(const float* __restrict__ in, const float* __restrict__ g,
                    const float* __restrict__ b, float* __restrict__ out)
{
    const int r = blockIdx.x;        // b * NH + h
    const int hd = r % NH;
    const int t = threadIdx.x;
    const float* xr = in + (size_t)r * HD;
    float v = xr[t];
    float mean = blockReduceSum256(v) * (1.0f / 256.0f);
    float d = v - mean;
    float var = blockReduceSum256(d * d) * (1.0f / 256.0f);
    float rstd = rsqrtf(var + 1e-5f);
    out[(size_t)r * HD + t] = d * rstd * g[hd * HD + t] + b[hd * HD + t];
}

// ---------------------------------------------------------------------------
// Launch
// ---------------------------------------------------------------------------
extern "C" void kernel_launch(void* const* d_in, const int* in_sizes, int n_in,
                              void* d_out, int out_size)
{
    (void)in_sizes; (void)n_in; (void)out_size;
    const float* x      = (const float*)d_in[0];
    const float* w_in   = (const float*)d_in[1];
    const float* b_in   = (const float*)d_in[2];
    const float* pos    = (const float*)d_in[3];
    const float* ln1_g  = (const float*)d_in[4];
    const float* ln1_b  = (const float*)d_in[5];
    const float* wv_sa  = (const float*)d_in[6];
    const float* bv_sa  = (const float*)d_in[7];
    const float* wo_sa  = (const float*)d_in[8];
    const float* bo_sa  = (const float*)d_in[9];
    /* ln2_g d_in[10], ln2_b d_in[11] unused (seq_len=1 collapse) */
    const float* wv_ca  = (const float*)d_in[12];
    const float* bv_ca  = (const float*)d_in[13];
    const float* wo_ca  = (const float*)d_in[14];
    const float* bo_ca  = (const float*)d_in[15];
    const float* ln3_g  = (const float*)d_in[16];
    const float* ln3_b  = (const float*)d_in[17];
    const float* w_ff1  = (const float*)d_in[18];
    const float* b_ff1  = (const float*)d_in[19];
    const float* w_ff2  = (const float*)d_in[20];
    const float* b_ff2  = (const float*)d_in[21];
    const float* lnoutg = (const float*)d_in[22];
    const float* lnoutb = (const float*)d_in[23];
    const float* wh1    = (const float*)d_in[24];
    const float* bh1    = (const float*)d_in[25];
    const float* lnh_g  = (const float*)d_in[26];
    const float* lnh_b  = (const float*)d_in[27];
    const float* wh2    = (const float*)d_in[28];
    const float* bh2    = (const float*)d_in[29];
    float* out = (float*)d_out;

    float *mem, *h, *t, *u, *ff, *z;
    cudaGetSymbolAddress((void**)&mem, g_mem);
    cudaGetSymbolAddress((void**)&h,   g_h);
    cudaGetSymbolAddress((void**)&t,   g_t);
    cudaGetSymbolAddress((void**)&u,   g_u);
    cudaGetSymbolAddress((void**)&ff,  g_ff);
    cudaGetSymbolAddress((void**)&z,   g_z);

    const dim3 blk(256);
    const int MB = BSZ / BM;   // 64

    // 1) mem = x @ w_in + b_in + pos
    sgemm_kernel<EPI_BIAS_POS><<<dim3(DMODEL / BN, MB), blk>>>(
        x, DIN, 0, w_in, DMODEL, 0, b_in, 0, pos, mem, DMODEL, 0, DIN);

    // 2) u = LN1(mem)
    ln512_kernel<<<BSZ, blk>>>(mem, ln1_g, ln1_b, u);

    // 3) t = u @ wv_sa + bv_sa
    sgemm_kernel<EPI_BIAS><<<dim3(DMODEL / BN, MB), blk>>>(
        u, DMODEL, 0, wv_sa, DMODEL, 0, bv_sa, 0, nullptr, t, DMODEL, 0, DMODEL);

    // 4) h = mem + (t @ wo_sa + bo_sa)
    sgemm_kernel<EPI_BIAS_ADD><<<dim3(DMODEL / BN, MB), blk>>>(
        t, DMODEL, 0, wo_sa, DMODEL, 0, bo_sa, 0, mem, h, DMODEL, 0, DMODEL);

    // 5) t = mem @ wv_ca + bv_ca
    sgemm_kernel<EPI_BIAS><<<dim3(DMODEL / BN, MB), blk>>>(
        mem, DMODEL, 0, wv_ca, DMODEL, 0, bv_ca, 0, nullptr, t, DMODEL, 0, DMODEL);

    // 6) h += t @ wo_ca + bo_ca   (in-place residual add)
    sgemm_kernel<EPI_BIAS_ADD><<<dim3(DMODEL / BN, MB), blk>>>(
        t, DMODEL, 0, wo_ca, DMODEL, 0, bo_ca, 0, h, h, DMODEL, 0, DMODEL);

    // 7) u = LN3(h)
    ln512_kernel<<<BSZ, blk>>>(h, ln3_g, ln3_b, u);

    // 8) ff = gelu(u @ w_ff1 + b_ff1)
    sgemm_kernel<EPI_BIAS_GELU><<<dim3(DFF / BN, MB), blk>>>(
        u, DMODEL, 0, w_ff1, DFF, 0, b_ff1, 0, nullptr, ff, DFF, 0, DMODEL);

    // 9) h += ff @ w_ff2 + b_ff2
    sgemm_kernel<EPI_BIAS_ADD><<<dim3(DMODEL / BN, MB), blk>>>(
        ff, DFF, 0, w_ff2, DMODEL, 0, b_ff2, 0, h, h, DMODEL, 0, DFF);

    // 10) u = LNout(h)
    ln512_kernel<<<BSZ, blk>>>(h, lnoutg, lnoutb, u);

    // 11) z[:,hd,:] = gelu(u @ wh1[hd] + bh1[hd])  -- all 3 heads in one launch
    sgemm_kernel<EPI_BIAS_GELU><<<dim3(HD / BN, MB, NH), blk>>>(
        u, DMODEL, 0,
        wh1, HD, (size_t)DMODEL * HD,
        bh1, HD, nullptr,
        z, NH * HD, HD, DMODEL);

    // 12) z = LN_head(z)  (in place)
    ln_head_kernel<<<BSZ * NH, blk>>>(z, lnh_g, lnh_b, z);

    // 13) out[:,hd,:] = z[:,hd,:] @ wh2[hd] + bh2[hd]  -- all 3 heads in one launch
    sgemm_kernel<EPI_BIAS><<<dim3(OUTD / BN, MB, NH), blk>>>(
        z, NH * HD, HD,
        wh2, OUTD, (size_t)HD * OUTD,
        bh2, OUTD, nullptr,
        out, NH * OUTD, OUTD, HD);
}

// round 4
// speedup vs baseline: 2.2335x; 2.2335x over previous
#include <cuda_runtime.h>
#include <cuda_bf16.h>
#include <math.h>
#include <stdint.h>

// ---------------------------------------------------------------------------
// Problem constants
// ---------------------------------------------------------------------------
#define BSZ    8192
#define DIN    4096
#define DMODEL 512
#define DFF    2048
#define NH     3
#define HD     256
#define OUTD   896

// ---------------------------------------------------------------------------
// Scratch (static device globals)
// ---------------------------------------------------------------------------
__device__ __align__(256) float g_mem[(size_t)BSZ * DMODEL];
__device__ __align__(256) float g_h  [(size_t)BSZ * DMODEL];
__device__ __align__(256) float g_t  [(size_t)BSZ * DMODEL];
__device__ __align__(256) float g_u  [(size_t)BSZ * DMODEL];
__device__ __align__(256) float g_ff [(size_t)BSZ * DFF];
__device__ __align__(256) float g_z  [(size_t)BSZ * NH * HD];

// Transposed + hi/lo-split weights pool (bf16, [N,K] K-major per weight)
#define WOFF_WIN   0u
#define WOFF_WVSA  2097152u
#define WOFF_WOSA  2359296u
#define WOFF_WVCA  2621440u
#define WOFF_WOCA  2883584u
#define WOFF_FF1   3145728u
#define WOFF_FF2   4194304u
#define WOFF_WH1   5242880u   // per head stride 131072
#define WOFF_WH2   5636096u   // per head stride 229376
#define WPOOL_ELEMS 6324224u
__device__ __align__(256) __nv_bfloat16 g_whi[WPOOL_ELEMS];
__device__ __align__(256) __nv_bfloat16 g_wlo[WPOOL_ELEMS];

// ---------------------------------------------------------------------------
// PTX helpers (baseline sm_80+ instructions only: ldmatrix / mma.sync / cp.async)
// ---------------------------------------------------------------------------
__device__ __forceinline__ uint32_t smem_u32(const void* p) {
    uint32_t a;
    asm("{ .reg .u64 t; cvta.to.shared.u64 t, %1; cvt.u32.u64 %0, t; }"
        : "=r"(a) : "l"(p));
    return a;
}

#define CP_ASYNC16(sdst, gsrc) \
    asm volatile("cp.async.ca.shared.global [%0], [%1], 16;" :: "r"(sdst), "l"(gsrc) : "memory")
#define CP_COMMIT() asm volatile("cp.async.commit_group;" ::: "memory")
#define CP_WAIT0()  asm volatile("cp.async.wait_group 0;" ::: "memory")

#define STS64(addr, v) \
    asm volatile("st.shared.b64 [%0], %1;" :: "r"(addr), "l"(v) : "memory")

#define LDM4(r, addr) \
    asm volatile("ldmatrix.sync.aligned.m8n8.x4.shared.b16 {%0,%1,%2,%3}, [%4];" \
        : "=r"((r)[0]), "=r"((r)[1]), "=r"((r)[2]), "=r"((r)[3]) : "r"(addr))

__device__ __forceinline__ void mma_bf16(float* c, const uint32_t* a, const uint32_t* b) {
    asm volatile(
        "mma.sync.aligned.m16n8k16.row.col.f32.bf16.bf16.f32 "
        "{%0,%1,%2,%3}, {%4,%5,%6,%7}, {%8,%9}, {%0,%1,%2,%3};"
        : "+f"(c[0]), "+f"(c[1]), "+f"(c[2]), "+f"(c[3])
        : "r"(a[0]), "r"(a[1]), "r"(a[2]), "r"(a[3]), "r"(b[0]), "r"(b[1]));
}

__device__ __forceinline__ float gelu_exact(float x) {
    return 0.5f * x * (1.0f + erff(x * 0.70710678118654752440f));
}
__device__ __forceinline__ void split2(float a, float b, uint32_t& hi, uint32_t& lo) {
    __nv_bfloat16 ha = __float2bfloat16_rn(a), hb = __float2bfloat16_rn(b);
    float ra = a - __bfloat162float(ha), rb = b - __bfloat162float(hb);
    __nv_bfloat16 la = __float2bfloat16_rn(ra), lb = __float2bfloat16_rn(rb);
    hi = (uint32_t)__bfloat16_as_ushort(ha) | ((uint32_t)__bfloat16_as_ushort(hb) << 16);
    lo = (uint32_t)__bfloat16_as_ushort(la) | ((uint32_t)__bfloat16_as_ushort(lb) << 16);
}

// ---------------------------------------------------------------------------
// Weight prep: src [K,N] fp32 -> dhi/dlo [N,K] bf16 (K-major)
// grid (N/32, K/32, Z), block (32,8)
// ---------------------------------------------------------------------------
__global__ __launch_bounds__(256)
void transpose_split_kernel(const float* __restrict__ src, size_t sSrc,
                            __nv_bfloat16* __restrict__ dhi,
                            __nv_bfloat16* __restrict__ dlo, size_t sDst,
                            int K, int N)
{
    __shared__ float tile[32][33];
    const int n0 = blockIdx.x * 32, k0 = blockIdx.y * 32, z = blockIdx.z;
    const int tx = threadIdx.x, ty = threadIdx.y;
    src += (size_t)z * sSrc; dhi += (size_t)z * sDst; dlo += (size_t)z * sDst;
#pragma unroll
    for (int i = 0; i < 4; i++)
        tile[ty + 8 * i][tx] = src[(size_t)(k0 + ty + 8 * i) * N + n0 + tx];
    __syncthreads();
#pragma unroll
    for (int i = 0; i < 4; i++) {
        const int n = n0 + ty + 8 * i, k = k0 + tx;
        float v = tile[tx][ty + 8 * i];
        __nv_bfloat16 h = __float2bfloat16_rn(v);
        float r = v - __bfloat162float(h);
        dhi[(size_t)n * K + k] = h;
        dlo[(size_t)n * K + k] = __float2bfloat16_rn(r);
    }
}

// ---------------------------------------------------------------------------
// mma.sync bf16x3 GEMM: C[M,N] = A_f32[M,K] @ W[K,N] + epilogue
// A: fp32 K-major (hi/lo split on the fly); W: pre-split [N,K] bf16 K-major.
// CTA tile 128x128, BK=32, double-buffered, 512 threads (16 warps, 4x4).
// SMEM stage layout (pitch 80B per 32-elem row):
//   Ahi @ +0 (10240B) | Alo @ +10240 | Bhi @ +20480 | Blo @ +30720  => 40960B
// ---------------------------------------------------------------------------
enum { EPI_BIAS = 0, EPI_BIAS_POS = 1, EPI_BIAS_ADD = 2, EPI_BIAS_GELU = 3 };

#define PITCH   80
#define STAGE_B 40960

template <int EPI>
__global__ __launch_bounds__(512)
void gemm_mma_kernel(const float* __restrict__ A, int lda, size_t sA,
                     const __nv_bfloat16* __restrict__ Bhi,
                     const __nv_bfloat16* __restrict__ Blo, int ldb, size_t sB,
                     const float* __restrict__ bias, size_t sBias,
                     const float* __restrict__ extra,
                     float* __restrict__ C, int ldc, size_t sC,
                     int K)
{
    extern __shared__ char smem[];
    const uint32_t db = smem_u32(smem);

    const int tid  = threadIdx.x;
    const int wid  = tid >> 5;
    const int lane = tid & 31;
    const int warp_m = wid & 3;       // 0..3 -> 32-row slice
    const int warp_n = wid >> 2;      // 0..3 -> 32-col slice
    const int m0 = blockIdx.y * 128;
    const int n0 = blockIdx.x * 128;
    const int bz = blockIdx.z;

    const float* Ab = A + (size_t)bz * sA + (size_t)m0 * lda;
    const __nv_bfloat16* Bh = Bhi + (size_t)bz * sB + (size_t)n0 * ldb;
    const __nv_bfloat16* Bl = Blo + (size_t)bz * sB + (size_t)n0 * ldb;

    float acc[2][4][4];
#pragma unroll
    for (int i = 0; i < 2; i++)
#pragma unroll
        for (int j = 0; j < 4; j++)
#pragma unroll
            for (int q = 0; q < 4; q++) acc[i][j][q] = 0.0f;

    // loader index precompute
    // A: 1024 float4 (128 rows x 8 float4); 2 per thread
    const int ar0 = (tid + 0)   >> 3, ac0 = ((tid + 0)   & 7) * 4;
    const int ar1 = (tid + 512) >> 3, ac1 = ((tid + 512) & 7) * 4;
    // B: 1024 16B-chunks (2 copies x 128 rows x 4 chunks); 2 per thread
    const int bidx0 = tid, bidx1 = tid + 512;
    const int bcopy0 = bidx0 >> 9, br0 = (bidx0 & 511) >> 2, bch0 = (bidx0 & 3);
    const int bcopy1 = bidx1 >> 9, br1 = (bidx1 & 511) >> 2, bch1 = (bidx1 & 3);

    const int S = K / 32;

    // ---- prologue: stage 0
    {
        const uint32_t st = db;
        {
            const __nv_bfloat16* s0 = (bcopy0 ? Bl : Bh) + (size_t)br0 * ldb + bch0 * 8;
            const __nv_bfloat16* s1 = (bcopy1 ? Bl : Bh) + (size_t)br1 * ldb + bch1 * 8;
            CP_ASYNC16(st + 20480 + bcopy0 * 10240 + br0 * PITCH + bch0 * 16, (const void*)s0);
            CP_ASYNC16(st + 20480 + bcopy1 * 10240 + br1 * PITCH + bch1 * 16, (const void*)s1);
            CP_COMMIT();
        }
        float4 v0 = *(const float4*)(Ab + (size_t)ar0 * lda + ac0);
        float4 v1 = *(const float4*)(Ab + (size_t)ar1 * lda + ac1);
        uint32_t h01, l01, h23, l23;
        split2(v0.x, v0.y, h01, l01); split2(v0.z, v0.w, h23, l23);
        STS64(st +         ar0 * PITCH + ac0 * 2, (uint64_t)h01 | ((uint64_t)h23 << 32));
        STS64(st + 10240 + ar0 * PITCH + ac0 * 2, (uint64_t)l01 | ((uint64_t)l23 << 32));
        split2(v1.x, v1.y, h01, l01); split2(v1.z, v1.w, h23, l23);
        STS64(st +         ar1 * PITCH + ac1 * 2, (uint64_t)h01 | ((uint64_t)h23 << 32));
        STS64(st + 10240 + ar1 * PITCH + ac1 * 2, (uint64_t)l01 | ((uint64_t)l23 << 32));
        CP_WAIT0();
        __syncthreads();
    }

    // ldmatrix address components (lane-dependent)
    const int a_row_in  = lane & 15;
    const int a_off     = (lane >> 4) << 4;
    const int b_row_in  = (lane & 7) + ((lane >> 4) << 3);
    const int b_off     = ((lane >> 3) & 1) << 4;

    for (int s = 0; s < S; s++) {
        const uint32_t cur = db + (uint32_t)(s & 1) * STAGE_B;
        const bool more = (s + 1 < S);
        float4 v0, v1;
        if (more) {
            const int k0 = (s + 1) * 32;
            const uint32_t nxt = db + (uint32_t)((s + 1) & 1) * STAGE_B;
            const __nv_bfloat16* s0 = (bcopy0 ? Bl : Bh) + (size_t)br0 * ldb + k0 + bch0 * 8;
            const __nv_bfloat16* s1 = (bcopy1 ? Bl : Bh) + (size_t)br1 * ldb + k0 + bch1 * 8;
            CP_ASYNC16(nxt + 20480 + bcopy0 * 10240 + br0 * PITCH + bch0 * 16, (const void*)s0);
            CP_ASYNC16(nxt + 20480 + bcopy1 * 10240 + br1 * PITCH + bch1 * 16, (const void*)s1);
            CP_COMMIT();
            v0 = *(const float4*)(Ab + (size_t)ar0 * lda + k0 + ac0);
            v1 = *(const float4*)(Ab + (size_t)ar1 * lda + k0 + ac1);
        }

        // ---- compute 2 k-steps from cur
#pragma unroll
        for (int kk = 0; kk < 2; kk++) {
            uint32_t ah[2][4], al[2][4], bh[2][4], bl[2][4];
#pragma unroll
            for (int mt = 0; mt < 2; mt++) {
                const uint32_t byte = (uint32_t)((warp_m * 32 + mt * 16 + a_row_in) * PITCH
                                                 + kk * 32 + a_off);
                LDM4(ah[mt], cur + byte);
                LDM4(al[mt], cur + 10240 + byte);
            }
#pragma unroll
            for (int nt = 0; nt < 2; nt++) {
                const uint32_t byte = (uint32_t)((warp_n * 32 + nt * 16 + b_row_in) * PITCH
                                                 + kk * 32 + b_off);
                LDM4(bh[nt], cur + 20480 + byte);
                LDM4(bl[nt], cur + 30720 + byte);
            }
#pragma unroll
            for (int mt = 0; mt < 2; mt++)
#pragma unroll
                for (int nt = 0; nt < 2; nt++)
#pragma unroll
                    for (int sub = 0; sub < 2; sub++) {
                        float* c = acc[mt][nt * 2 + sub];
                        mma_bf16(c, ah[mt], &bh[nt][sub * 2]);
                        mma_bf16(c, ah[mt], &bl[nt][sub * 2]);
                        mma_bf16(c, al[mt], &bh[nt][sub * 2]);
                    }
        }

        if (more) {
            const uint32_t nxt = db + (uint32_t)((s + 1) & 1) * STAGE_B;
            uint32_t h01, l01, h23, l23;
            split2(v0.x, v0.y, h01, l01); split2(v0.z, v0.w, h23, l23);
            STS64(nxt +         ar0 * PITCH + ac0 * 2, (uint64_t)h01 | ((uint64_t)h23 << 32));
            STS64(nxt + 10240 + ar0 * PITCH + ac0 * 2, (uint64_t)l01 | ((uint64_t)l23 << 32));
            split2(v1.x, v1.y, h01, l01); split2(v1.z, v1.w, h23, l23);
            STS64(nxt +         ar1 * PITCH + ac1 * 2, (uint64_t)h01 | ((uint64_t)h23 << 32));
            STS64(nxt + 10240 + ar1 * PITCH + ac1 * 2, (uint64_t)l01 | ((uint64_t)l23 << 32));
            CP_WAIT0();
            __syncthreads();
        }
    }

    // ---- epilogue
    const float* biasb = bias + (size_t)bz * sBias + n0;
    const float* posb  = (EPI == EPI_BIAS_POS) ? extra + n0 : nullptr;
#pragma unroll
    for (int mt = 0; mt < 2; mt++) {
#pragma unroll
        for (int half = 0; half < 2; half++) {
            const int m = m0 + warp_m * 32 + mt * 16 + (lane >> 2) + half * 8;
            float* Crow = C + (size_t)bz * sC + (size_t)m * ldc + n0;
            const float* Erow = (EPI == EPI_BIAS_ADD)
                              ? extra + (size_t)m * ldc + n0 : nullptr;
#pragma unroll
            for (int nt = 0; nt < 4; nt++) {
                const int n = warp_n * 32 + nt * 8 + (lane & 3) * 2;
                float va = acc[mt][nt][half * 2 + 0] + biasb[n + 0];
                float vb = acc[mt][nt][half * 2 + 1] + biasb[n + 1];
                if (EPI == EPI_BIAS_POS) { va += posb[n]; vb += posb[n + 1]; }
                if (EPI == EPI_BIAS_ADD) {
                    float2 e = *(const float2*)(Erow + n);
                    va += e.x; vb += e.y;
                }
                if (EPI == EPI_BIAS_GELU) { va = gelu_exact(va); vb = gelu_exact(vb); }
                float2 o; o.x = va; o.y = vb;
                *(float2*)(Crow + n) = o;
            }
        }
    }
}

// ---------------------------------------------------------------------------
// LayerNorm kernels (fp32, known-good)
// ---------------------------------------------------------------------------
__device__ __forceinline__ float blockReduceSum256(float v) {
    __shared__ float sh[8];
    const int lane = threadIdx.x & 31, wid = threadIdx.x >> 5;
#pragma unroll
    for (int o = 16; o > 0; o >>= 1) v += __shfl_xor_sync(0xffffffffu, v, o);
    if (lane == 0) sh[wid] = v;
    __syncthreads();
    float r;
    if (wid == 0) {
        r = sh[lane & 7];
#pragma unroll
        for (int o = 4; o > 0; o >>= 1) r += __shfl_xor_sync(0xffffffffu, r, o);
        if (lane == 0) sh[0] = r;
    }
    __syncthreads();
    r = sh[0];
    __syncthreads();
    return r;
}

__global__ __launch_bounds__(256)
void ln512_kernel(const float* __restrict__ in, const float* __restrict__ g,
                  const float* __restrict__ b, float* __restrict__ out)
{
    const int r = blockIdx.x, t = threadIdx.x;
    const float* xr = in + (size_t)r * DMODEL;
    float v0 = xr[t], v1 = xr[t + 256];
    float mean = blockReduceSum256(v0 + v1) * (1.0f / 512.0f);
    float d0 = v0 - mean, d1 = v1 - mean;
    float var = blockReduceSum256(d0 * d0 + d1 * d1) * (1.0f / 512.0f);
    float rstd = rsqrtf(var + 1e-5f);
    float* orow = out + (size_t)r * DMODEL;
    orow[t]       = d0 * rstd * g[t]       + b[t];
    orow[t + 256] = d1 * rstd * g[t + 256] + b[t + 256];
}

__global__ __launch_bounds__(256)
void ln_head_kernel(const float* __restrict__ in, const float* __restrict__ g,
                    const float* __restrict__ b, float* __restrict__ out)
{
    const int r = blockIdx.x, hd = r % NH, t = threadIdx.x;
    const float* xr = in + (size_t)r * HD;
    float v = xr[t];
    float mean = blockReduceSum256(v) * (1.0f / 256.0f);
    float d = v - mean;
    float var = blockReduceSum256(d * d) * (1.0f / 256.0f);
    float rstd = rsqrtf(var + 1e-5f);
    out[(size_t)r * HD + t] = d * rstd * g[hd * HD + t] + b[hd * HD + t];
}

// ---------------------------------------------------------------------------
// Launch
// ---------------------------------------------------------------------------
#define GEMM_SMEM (2 * STAGE_B)

extern "C" void kernel_launch(void* const* d_in, const int* in_sizes, int n_in,
                              void* d_out, int out_size)
{
    (void)in_sizes; (void)n_in; (void)out_size;
    const float* x      = (const float*)d_in[0];
    const float* w_in   = (const float*)d_in[1];
    const float* b_in   = (const float*)d_in[2];
    const float* pos    = (const float*)d_in[3];
    const float* ln1_g  = (const float*)d_in[4];
    const float* ln1_b  = (const float*)d_in[5];
    const float* wv_sa  = (const float*)d_in[6];
    const float* bv_sa  = (const float*)d_in[7];
    const float* wo_sa  = (const float*)d_in[8];
    const float* bo_sa  = (const float*)d_in[9];
    const float* wv_ca  = (const float*)d_in[12];
    const float* bv_ca  = (const float*)d_in[13];
    const float* wo_ca  = (const float*)d_in[14];
    const float* bo_ca  = (const float*)d_in[15];
    const float* ln3_g  = (const float*)d_in[16];
    const float* ln3_b  = (const float*)d_in[17];
    const float* w_ff1  = (const float*)d_in[18];
    const float* b_ff1  = (const float*)d_in[19];
    const float* w_ff2  = (const float*)d_in[20];
    const float* b_ff2  = (const float*)d_in[21];
    const float* lnoutg = (const float*)d_in[22];
    const float* lnoutb = (const float*)d_in[23];
    const float* wh1    = (const float*)d_in[24];
    const float* bh1    = (const float*)d_in[25];
    const float* lnh_g  = (const float*)d_in[26];
    const float* lnh_b  = (const float*)d_in[27];
    const float* wh2    = (const float*)d_in[28];
    const float* bh2    = (const float*)d_in[29];
    float* out = (float*)d_out;

    float *mem, *h, *t, *u, *ff, *z;
    __nv_bfloat16 *whi, *wlo;
    cudaGetSymbolAddress((void**)&mem, g_mem);
    cudaGetSymbolAddress((void**)&h,   g_h);
    cudaGetSymbolAddress((void**)&t,   g_t);
    cudaGetSymbolAddress((void**)&u,   g_u);
    cudaGetSymbolAddress((void**)&ff,  g_ff);
    cudaGetSymbolAddress((void**)&z,   g_z);
    cudaGetSymbolAddress((void**)&whi, g_whi);
    cudaGetSymbolAddress((void**)&wlo, g_wlo);

    cudaFuncSetAttribute(gemm_mma_kernel<EPI_BIAS>,      cudaFuncAttributeMaxDynamicSharedMemorySize, GEMM_SMEM);
    cudaFuncSetAttribute(gemm_mma_kernel<EPI_BIAS_POS>,  cudaFuncAttributeMaxDynamicSharedMemorySize, GEMM_SMEM);
    cudaFuncSetAttribute(gemm_mma_kernel<EPI_BIAS_ADD>,  cudaFuncAttributeMaxDynamicSharedMemorySize, GEMM_SMEM);
    cudaFuncSetAttribute(gemm_mma_kernel<EPI_BIAS_GELU>, cudaFuncAttributeMaxDynamicSharedMemorySize, GEMM_SMEM);

    const dim3 gblk(512);
    const dim3 lblk(256);
    const dim3 tblk(32, 8);
    const int MB = BSZ / 128;   // 64

    // ---- weight prep: transpose + hi/lo split
    transpose_split_kernel<<<dim3(DMODEL/32, DIN/32),   tblk>>>(w_in,  0, whi+WOFF_WIN,  wlo+WOFF_WIN,  0, DIN,    DMODEL);
    transpose_split_kernel<<<dim3(DMODEL/32, DMODEL/32),tblk>>>(wv_sa, 0, whi+WOFF_WVSA, wlo+WOFF_WVSA, 0, DMODEL, DMODEL);
    transpose_split_kernel<<<dim3(DMODEL/32, DMODEL/32),tblk>>>(wo_sa, 0, whi+WOFF_WOSA, wlo+WOFF_WOSA, 0, DMODEL, DMODEL);
    transpose_split_kernel<<<dim3(DMODEL/32, DMODEL/32),tblk>>>(wv_ca, 0, whi+WOFF_WVCA, wlo+WOFF_WVCA, 0, DMODEL, DMODEL);
    transpose_split_kernel<<<dim3(DMODEL/32, DMODEL/32),tblk>>>(wo_ca, 0, whi+WOFF_WOCA, wlo+WOFF_WOCA, 0, DMODEL, DMODEL);
    transpose_split_kernel<<<dim3(DFF/32,    DMODEL/32),tblk>>>(w_ff1, 0, whi+WOFF_FF1,  wlo+WOFF_FF1,  0, DMODEL, DFF);
    transpose_split_kernel<<<dim3(DMODEL/32, DFF/32),   tblk>>>(w_ff2, 0, whi+WOFF_FF2,  wlo+WOFF_FF2,  0, DFF,    DMODEL);
    transpose_split_kernel<<<dim3(HD/32, DMODEL/32, NH),tblk>>>(wh1, (size_t)DMODEL*HD, whi+WOFF_WH1, wlo+WOFF_WH1, 131072, DMODEL, HD);
    transpose_split_kernel<<<dim3(OUTD/32, HD/32, NH),  tblk>>>(wh2, (size_t)HD*OUTD,   whi+WOFF_WH2, wlo+WOFF_WH2, 229376, HD,     OUTD);

    // 1) mem = x @ w_in + b_in + pos
    gemm_mma_kernel<EPI_BIAS_POS><<<dim3(DMODEL/128, MB), gblk, GEMM_SMEM>>>(
        x, DIN, 0, whi+WOFF_WIN, wlo+WOFF_WIN, DIN, 0, b_in, 0, pos, mem, DMODEL, 0, DIN);
    // 2) u = LN1(mem)
    ln512_kernel<<<BSZ, lblk>>>(mem, ln1_g, ln1_b, u);
    // 3) t = u @ wv_sa + bv_sa
    gemm_mma_kernel<EPI_BIAS><<<dim3(DMODEL/128, MB), gblk, GEMM_SMEM>>>(
        u, DMODEL, 0, whi+WOFF_WVSA, wlo+WOFF_WVSA, DMODEL, 0, bv_sa, 0, nullptr, t, DMODEL, 0, DMODEL);
    // 4) h = mem + t @ wo_sa + bo_sa
    gemm_mma_kernel<EPI_BIAS_ADD><<<dim3(DMODEL/128, MB), gblk, GEMM_SMEM>>>(
        t, DMODEL, 0, whi+WOFF_WOSA, wlo+WOFF_WOSA, DMODEL, 0, bo_sa, 0, mem, h, DMODEL, 0, DMODEL);
    // 5) t = mem @ wv_ca + bv_ca
    gemm_mma_kernel<EPI_BIAS><<<dim3(DMODEL/128, MB), gblk, GEMM_SMEM>>>(
        mem, DMODEL, 0, whi+WOFF_WVCA, wlo+WOFF_WVCA, DMODEL, 0, bv_ca, 0, nullptr, t, DMODEL, 0, DMODEL);
    // 6) h += t @ wo_ca + bo_ca
    gemm_mma_kernel<EPI_BIAS_ADD><<<dim3(DMODEL/128, MB), gblk, GEMM_SMEM>>>(
        t, DMODEL, 0, whi+WOFF_WOCA, wlo+WOFF_WOCA, DMODEL, 0, bo_ca, 0, h, h, DMODEL, 0, DMODEL);
    // 7) u = LN3(h)
    ln512_kernel<<<BSZ, lblk>>>(h, ln3_g, ln3_b, u);
    // 8) ff = gelu(u @ w_ff1 + b_ff1)
    gemm_mma_kernel<EPI_BIAS_GELU><<<dim3(DFF/128, MB), gblk, GEMM_SMEM>>>(
        u, DMODEL, 0, whi+WOFF_FF1, wlo+WOFF_FF1, DMODEL, 0, b_ff1, 0, nullptr, ff, DFF, 0, DMODEL);
    // 9) h += ff @ w_ff2 + b_ff2
    gemm_mma_kernel<EPI_BIAS_ADD><<<dim3(DMODEL/128, MB), gblk, GEMM_SMEM>>>(
        ff, DFF, 0, whi+WOFF_FF2, wlo+WOFF_FF2, DFF, 0, b_ff2, 0, h, h, DMODEL, 0, DFF);
    // 10) u = LNout(h)
    ln512_kernel<<<BSZ, lblk>>>(h, lnoutg, lnoutb, u);
    // 11) z = gelu(u @ wh1 + bh1)   (heads batched over z)
    gemm_mma_kernel<EPI_BIAS_GELU><<<dim3(HD/128, MB, NH), gblk, GEMM_SMEM>>>(
        u, DMODEL, 0, whi+WOFF_WH1, wlo+WOFF_WH1, DMODEL, 131072, bh1, HD, nullptr, z, NH*HD, HD, DMODEL);
    // 12) z = LN_head(z)
    ln_head_kernel<<<BSZ * NH, lblk>>>(z, lnh_g, lnh_b, z);
    // 13) out = z @ wh2 + bh2
    gemm_mma_kernel<EPI_BIAS><<<dim3(OUTD/128, MB, NH), gblk, GEMM_SMEM>>>(
        z, NH*HD, HD, whi+WOFF_WH2, wlo+WOFF_WH2, HD, 229376, bh2, OUTD, nullptr, out, NH*OUTD, OUTD, HD);
}